// round 6
// baseline (speedup 1.0000x reference)
#include <cuda_runtime.h>

#define BB 20
#define SS 4096
#define EE 256
#define NB 32
#define BLK 128
#define CTX 384
#define ROWS (BB*SS)   // 81920

// Scratch (device globals: no allocation allowed in kernel_launch)
__device__ float g_q[BB*SS*EE];
__device__ float g_k[BB*SS*EE];
__device__ float g_v[BB*SS*EE];
__device__ float g_att[BB*SS*EE];
__device__ float g_logits[(size_t)BB*NB*BLK*CTX];

// ---------------------------------------------------------------------------
// Fused QKV projection: [81920,256] @ [256,256] for each of Wq/Wk/Wv.
// grid (640, 6): y>>1 selects matrix, y&1 selects 128-col half.
// ---------------------------------------------------------------------------
__global__ __launch_bounds__(256) void qkv_kernel(const float* __restrict__ x,
                                                  const float* __restrict__ Wq,
                                                  const float* __restrict__ Wk,
                                                  const float* __restrict__ Wv)
{
    __shared__ float As[16][128];
    __shared__ float Bs[16][128];
    const int tid = threadIdx.x;
    const int tx = tid & 15, ty = tid >> 4;
    const int m0 = blockIdx.x * 128;
    const int sel = blockIdx.y >> 1;
    const int col0 = (blockIdx.y & 1) * 128;
    const float* W = (sel == 0) ? Wq : ((sel == 1) ? Wk : Wv);
    float* out = (sel == 0) ? g_q : ((sel == 1) ? g_k : g_v);

    float acc[8][8];
#pragma unroll
    for (int i = 0; i < 8; i++)
#pragma unroll
        for (int j = 0; j < 8; j++) acc[i][j] = 0.f;

    for (int kt = 0; kt < EE; kt += 16) {
        // A (x) transposed load: 128 rows x 16 cols -> As[kk][m]
#pragma unroll
        for (int t = 0; t < 2; t++) {
            int f4 = tid + 256 * t;
            int row = f4 >> 2, c4 = f4 & 3;
            float4 v = *(const float4*)(x + (size_t)(m0 + row) * EE + kt + c4 * 4);
            As[c4 * 4 + 0][row] = v.x; As[c4 * 4 + 1][row] = v.y;
            As[c4 * 4 + 2][row] = v.z; As[c4 * 4 + 3][row] = v.w;
        }
        // B (W) natural load: 16 rows x 128 cols
#pragma unroll
        for (int t = 0; t < 2; t++) {
            int f4 = tid + 256 * t;
            int row = f4 >> 5, c4 = f4 & 31;
            float4 v = *(const float4*)(W + (size_t)(kt + row) * EE + col0 + c4 * 4);
            *(float4*)&Bs[row][c4 * 4] = v;
        }
        __syncthreads();
#pragma unroll
        for (int kk = 0; kk < 16; kk++) {
            float4 a0 = *(float4*)&As[kk][ty * 4];
            float4 a1 = *(float4*)&As[kk][ty * 4 + 64];
            float4 b0 = *(float4*)&Bs[kk][tx * 4];
            float4 b1 = *(float4*)&Bs[kk][tx * 4 + 64];
            float a[8] = {a0.x, a0.y, a0.z, a0.w, a1.x, a1.y, a1.z, a1.w};
            float b[8] = {b0.x, b0.y, b0.z, b0.w, b1.x, b1.y, b1.z, b1.w};
#pragma unroll
            for (int i = 0; i < 8; i++)
#pragma unroll
                for (int j = 0; j < 8; j++) acc[i][j] += a[i] * b[j];
        }
        __syncthreads();
    }
#pragma unroll
    for (int ii = 0; ii < 2; ii++)
#pragma unroll
        for (int i = 0; i < 4; i++) {
            int row = m0 + ty * 4 + 64 * ii + i;
#pragma unroll
            for (int jj = 0; jj < 2; jj++) {
                float4 v = make_float4(acc[ii * 4 + i][jj * 4 + 0], acc[ii * 4 + i][jj * 4 + 1],
                                       acc[ii * 4 + i][jj * 4 + 2], acc[ii * 4 + i][jj * 4 + 3]);
                *(float4*)(out + (size_t)row * EE + col0 + tx * 4 + 64 * jj) = v;
            }
        }
}

// ---------------------------------------------------------------------------
// Logits: per (b,n,w) 128x128 tile of q_b @ k_{n-1+w}^T / 16.
// Out-of-range context block -> logits are literal zeros (matches zero-pad).
// grid (640, 3)
// ---------------------------------------------------------------------------
__global__ __launch_bounds__(256) void logits_kernel()
{
    const int tid = threadIdx.x;
    const int tx = tid & 15, ty = tid >> 4;
    const int bn = blockIdx.x;
    const int b = bn >> 5, n = bn & 31;
    const int w = blockIdx.y;
    const int j = n - 1 + w;
    float* Lbase = g_logits + (size_t)bn * (BLK * CTX) + w * 128;

    if (j < 0 || j >= NB) {
#pragma unroll
        for (int t = 0; t < 16; t++) {
            int f4 = tid + 256 * t;
            int row = f4 >> 5, c4 = f4 & 31;
            *(float4*)(Lbase + (size_t)row * CTX + c4 * 4) = make_float4(0.f, 0.f, 0.f, 0.f);
        }
        return;
    }

    __shared__ float As[16][128];
    __shared__ float Bs[16][128];
    const float* Abase = g_q + (size_t)(b * SS + n * 128) * EE;
    const float* Kbase = g_k + (size_t)(b * SS + j * 128) * EE;

    float acc[8][8];
#pragma unroll
    for (int i = 0; i < 8; i++)
#pragma unroll
        for (int jq = 0; jq < 8; jq++) acc[i][jq] = 0.f;

    for (int kt = 0; kt < EE; kt += 16) {
        // both operands transposed-load (NT gemm)
#pragma unroll
        for (int t = 0; t < 2; t++) {
            int f4 = tid + 256 * t;
            int row = f4 >> 2, c4 = f4 & 3;
            float4 va = *(const float4*)(Abase + (size_t)row * EE + kt + c4 * 4);
            As[c4 * 4 + 0][row] = va.x; As[c4 * 4 + 1][row] = va.y;
            As[c4 * 4 + 2][row] = va.z; As[c4 * 4 + 3][row] = va.w;
            float4 vb = *(const float4*)(Kbase + (size_t)row * EE + kt + c4 * 4);
            Bs[c4 * 4 + 0][row] = vb.x; Bs[c4 * 4 + 1][row] = vb.y;
            Bs[c4 * 4 + 2][row] = vb.z; Bs[c4 * 4 + 3][row] = vb.w;
        }
        __syncthreads();
#pragma unroll
        for (int kk = 0; kk < 16; kk++) {
            float4 a0 = *(float4*)&As[kk][ty * 4];
            float4 a1 = *(float4*)&As[kk][ty * 4 + 64];
            float4 b0 = *(float4*)&Bs[kk][tx * 4];
            float4 b1 = *(float4*)&Bs[kk][tx * 4 + 64];
            float a[8] = {a0.x, a0.y, a0.z, a0.w, a1.x, a1.y, a1.z, a1.w};
            float bq[8] = {b0.x, b0.y, b0.z, b0.w, b1.x, b1.y, b1.z, b1.w};
#pragma unroll
            for (int i = 0; i < 8; i++)
#pragma unroll
                for (int jq = 0; jq < 8; jq++) acc[i][jq] += a[i] * bq[jq];
        }
        __syncthreads();
    }
    const float scale = 0.0625f;  // 1/sqrt(256)
#pragma unroll
    for (int ii = 0; ii < 2; ii++)
#pragma unroll
        for (int i = 0; i < 4; i++) {
            int row = ty * 4 + 64 * ii + i;
#pragma unroll
            for (int jj = 0; jj < 2; jj++) {
                float4 v = make_float4(acc[ii * 4 + i][jj * 4 + 0] * scale,
                                       acc[ii * 4 + i][jj * 4 + 1] * scale,
                                       acc[ii * 4 + i][jj * 4 + 2] * scale,
                                       acc[ii * 4 + i][jj * 4 + 3] * scale);
                *(float4*)(Lbase + (size_t)row * CTX + tx * 4 + 64 * jj) = v;
            }
        }
}

// ---------------------------------------------------------------------------
// Softmax over 384, one warp per row (81920 rows).
// ---------------------------------------------------------------------------
__global__ __launch_bounds__(256) void softmax_kernel()
{
    const int gw = (blockIdx.x * blockDim.x + threadIdx.x) >> 5;
    const int lane = threadIdx.x & 31;
    float* row = g_logits + (size_t)gw * CTX;
    float v[12];
    float mx = -1e30f;
#pragma unroll
    for (int i = 0; i < 12; i++) { v[i] = row[lane + 32 * i]; mx = fmaxf(mx, v[i]); }
#pragma unroll
    for (int o = 16; o > 0; o >>= 1) mx = fmaxf(mx, __shfl_xor_sync(0xFFFFFFFFu, mx, o));
    float s = 0.f;
#pragma unroll
    for (int i = 0; i < 12; i++) { v[i] = __expf(v[i] - mx); s += v[i]; }
#pragma unroll
    for (int o = 16; o > 0; o >>= 1) s += __shfl_xor_sync(0xFFFFFFFFu, s, o);
    float inv = 1.f / s;
#pragma unroll
    for (int i = 0; i < 12; i++) row[lane + 32 * i] = v[i] * inv;
}

// ---------------------------------------------------------------------------
// AV: per (b,n): [128,384] @ vc[384,256]; out-of-range V rows read as zero.
// Output written at permuted row n*(B*128) + b*128 + q  (matches reference
// transpose(1,0,2,3).reshape).  grid (640, 2)
// ---------------------------------------------------------------------------
__global__ __launch_bounds__(256) void av_kernel()
{
    __shared__ float As[16][128];
    __shared__ float Bs[16][128];
    const int tid = threadIdx.x;
    const int tx = tid & 15, ty = tid >> 4;
    const int bn = blockIdx.x;
    const int b = bn >> 5, n = bn & 31;
    const int n0 = blockIdx.y * 128;
    const float* Abase = g_logits + (size_t)bn * (BLK * CTX);
    const int srow_base = (n - 1) * 128;

    float acc[8][8];
#pragma unroll
    for (int i = 0; i < 8; i++)
#pragma unroll
        for (int j = 0; j < 8; j++) acc[i][j] = 0.f;

    for (int kt = 0; kt < CTX; kt += 16) {
#pragma unroll
        for (int t = 0; t < 2; t++) {
            int f4 = tid + 256 * t;
            int row = f4 >> 2, c4 = f4 & 3;
            float4 v = *(const float4*)(Abase + (size_t)row * CTX + kt + c4 * 4);
            As[c4 * 4 + 0][row] = v.x; As[c4 * 4 + 1][row] = v.y;
            As[c4 * 4 + 2][row] = v.z; As[c4 * 4 + 3][row] = v.w;
        }
#pragma unroll
        for (int t = 0; t < 2; t++) {
            int f4 = tid + 256 * t;
            int row = f4 >> 5, c4 = f4 & 31;
            int sr = srow_base + kt + row;
            float4 v = make_float4(0.f, 0.f, 0.f, 0.f);
            if (sr >= 0 && sr < SS)
                v = *(const float4*)(g_v + (size_t)(b * SS + sr) * EE + n0 + c4 * 4);
            *(float4*)&Bs[row][c4 * 4] = v;
        }
        __syncthreads();
#pragma unroll
        for (int kk = 0; kk < 16; kk++) {
            float4 a0 = *(float4*)&As[kk][ty * 4];
            float4 a1 = *(float4*)&As[kk][ty * 4 + 64];
            float4 b0 = *(float4*)&Bs[kk][tx * 4];
            float4 b1 = *(float4*)&Bs[kk][tx * 4 + 64];
            float a[8] = {a0.x, a0.y, a0.z, a0.w, a1.x, a1.y, a1.z, a1.w};
            float bv[8] = {b0.x, b0.y, b0.z, b0.w, b1.x, b1.y, b1.z, b1.w};
#pragma unroll
            for (int i = 0; i < 8; i++)
#pragma unroll
                for (int j = 0; j < 8; j++) acc[i][j] += a[i] * bv[j];
        }
        __syncthreads();
    }
    const int orow_base = n * (BB * 128) + b * 128;
#pragma unroll
    for (int ii = 0; ii < 2; ii++)
#pragma unroll
        for (int i = 0; i < 4; i++) {
            int row = orow_base + ty * 4 + 64 * ii + i;
#pragma unroll
            for (int jj = 0; jj < 2; jj++) {
                float4 v = make_float4(acc[ii * 4 + i][jj * 4 + 0], acc[ii * 4 + i][jj * 4 + 1],
                                       acc[ii * 4 + i][jj * 4 + 2], acc[ii * 4 + i][jj * 4 + 3]);
                *(float4*)(g_att + (size_t)row * EE + n0 + tx * 4 + 64 * jj) = v;
            }
        }
}

// ---------------------------------------------------------------------------
// Output projection: [81920,256] @ Wo[256,256] + bo -> d_out.  grid (640, 2)
// ---------------------------------------------------------------------------
__global__ __launch_bounds__(256) void out_kernel(const float* __restrict__ Wo,
                                                  const float* __restrict__ bo,
                                                  float* __restrict__ out)
{
    __shared__ float As[16][128];
    __shared__ float Bs[16][128];
    const int tid = threadIdx.x;
    const int tx = tid & 15, ty = tid >> 4;
    const int m0 = blockIdx.x * 128;
    const int n0 = blockIdx.y * 128;

    float acc[8][8];
#pragma unroll
    for (int i = 0; i < 8; i++)
#pragma unroll
        for (int j = 0; j < 8; j++) acc[i][j] = 0.f;

    for (int kt = 0; kt < EE; kt += 16) {
#pragma unroll
        for (int t = 0; t < 2; t++) {
            int f4 = tid + 256 * t;
            int row = f4 >> 2, c4 = f4 & 3;
            float4 v = *(const float4*)(g_att + (size_t)(m0 + row) * EE + kt + c4 * 4);
            As[c4 * 4 + 0][row] = v.x; As[c4 * 4 + 1][row] = v.y;
            As[c4 * 4 + 2][row] = v.z; As[c4 * 4 + 3][row] = v.w;
        }
#pragma unroll
        for (int t = 0; t < 2; t++) {
            int f4 = tid + 256 * t;
            int row = f4 >> 5, c4 = f4 & 31;
            float4 v = *(const float4*)(Wo + (size_t)(kt + row) * EE + n0 + c4 * 4);
            *(float4*)&Bs[row][c4 * 4] = v;
        }
        __syncthreads();
#pragma unroll
        for (int kk = 0; kk < 16; kk++) {
            float4 a0 = *(float4*)&As[kk][ty * 4];
            float4 a1 = *(float4*)&As[kk][ty * 4 + 64];
            float4 b0 = *(float4*)&Bs[kk][tx * 4];
            float4 b1 = *(float4*)&Bs[kk][tx * 4 + 64];
            float a[8] = {a0.x, a0.y, a0.z, a0.w, a1.x, a1.y, a1.z, a1.w};
            float bw[8] = {b0.x, b0.y, b0.z, b0.w, b1.x, b1.y, b1.z, b1.w};
#pragma unroll
            for (int i = 0; i < 8; i++)
#pragma unroll
                for (int j = 0; j < 8; j++) acc[i][j] += a[i] * bw[j];
        }
        __syncthreads();
    }
    float4 bias0 = *(const float4*)(bo + n0 + tx * 4);
    float4 bias1 = *(const float4*)(bo + n0 + tx * 4 + 64);
#pragma unroll
    for (int ii = 0; ii < 2; ii++)
#pragma unroll
        for (int i = 0; i < 4; i++) {
            int row = m0 + ty * 4 + 64 * ii + i;
            float4 v0 = make_float4(acc[ii * 4 + i][0] + bias0.x, acc[ii * 4 + i][1] + bias0.y,
                                    acc[ii * 4 + i][2] + bias0.z, acc[ii * 4 + i][3] + bias0.w);
            float4 v1 = make_float4(acc[ii * 4 + i][4] + bias1.x, acc[ii * 4 + i][5] + bias1.y,
                                    acc[ii * 4 + i][6] + bias1.z, acc[ii * 4 + i][7] + bias1.w);
            *(float4*)(out + (size_t)row * EE + n0 + tx * 4) = v0;
            *(float4*)(out + (size_t)row * EE + n0 + tx * 4 + 64) = v1;
        }
}

extern "C" void kernel_launch(void* const* d_in, const int* in_sizes, int n_in,
                              void* d_out, int out_size)
{
    const float* x  = (const float*)d_in[0];
    const float* Wq = (const float*)d_in[1];
    const float* Wk = (const float*)d_in[2];
    const float* Wv = (const float*)d_in[3];
    const float* Wo = (const float*)d_in[4];
    const float* bo = (const float*)d_in[5];
    float* out = (float*)d_out;

    qkv_kernel<<<dim3(640, 6), 256>>>(x, Wq, Wk, Wv);
    logits_kernel<<<dim3(640, 3), 256>>>();
    softmax_kernel<<<dim3(10240), 256>>>();
    av_kernel<<<dim3(640, 2), 256>>>();
    out_kernel<<<dim3(640, 2), 256>>>(Wo, bo, out);
}

// round 9
// speedup vs baseline: 1.0008x; 1.0008x over previous
#include <cuda_runtime.h>

#define BB 20
#define SS 4096
#define EE 256
#define NB 32
#define BLK 128
#define CTX 384
#define ROWS (BB*SS)   // 81920

// Scratch (device globals: no allocation allowed in kernel_launch)
__device__ float g_q[BB*SS*EE];
__device__ float g_k[BB*SS*EE];
__device__ float g_v[BB*SS*EE];
__device__ float g_att[BB*SS*EE];
__device__ float g_logits[(size_t)BB*NB*BLK*CTX];

// ---------------------------------------------------------------------------
// Fused QKV projection: [81920,256] @ [256,256] for each of Wq/Wk/Wv.
// grid (640, 6): y>>1 selects matrix, y&1 selects 128-col half.
// ---------------------------------------------------------------------------
__global__ __launch_bounds__(256) void qkv_kernel(const float* __restrict__ x,
                                                  const float* __restrict__ Wq,
                                                  const float* __restrict__ Wk,
                                                  const float* __restrict__ Wv)
{
    __shared__ float As[16][128];
    __shared__ float Bs[16][128];
    const int tid = threadIdx.x;
    const int tx = tid & 15, ty = tid >> 4;
    const int m0 = blockIdx.x * 128;
    const int sel = blockIdx.y >> 1;
    const int col0 = (blockIdx.y & 1) * 128;
    const float* W = (sel == 0) ? Wq : ((sel == 1) ? Wk : Wv);
    float* out = (sel == 0) ? g_q : ((sel == 1) ? g_k : g_v);

    float acc[8][8];
#pragma unroll
    for (int i = 0; i < 8; i++)
#pragma unroll
        for (int j = 0; j < 8; j++) acc[i][j] = 0.f;

    for (int kt = 0; kt < EE; kt += 16) {
        // A (x) transposed load: 128 rows x 16 cols -> As[kk][m]
#pragma unroll
        for (int t = 0; t < 2; t++) {
            int f4 = tid + 256 * t;
            int row = f4 >> 2, c4 = f4 & 3;
            float4 v = *(const float4*)(x + (size_t)(m0 + row) * EE + kt + c4 * 4);
            As[c4 * 4 + 0][row] = v.x; As[c4 * 4 + 1][row] = v.y;
            As[c4 * 4 + 2][row] = v.z; As[c4 * 4 + 3][row] = v.w;
        }
        // B (W) natural load: 16 rows x 128 cols
#pragma unroll
        for (int t = 0; t < 2; t++) {
            int f4 = tid + 256 * t;
            int row = f4 >> 5, c4 = f4 & 31;
            float4 v = *(const float4*)(W + (size_t)(kt + row) * EE + col0 + c4 * 4);
            *(float4*)&Bs[row][c4 * 4] = v;
        }
        __syncthreads();
#pragma unroll
        for (int kk = 0; kk < 16; kk++) {
            float4 a0 = *(float4*)&As[kk][ty * 4];
            float4 a1 = *(float4*)&As[kk][ty * 4 + 64];
            float4 b0 = *(float4*)&Bs[kk][tx * 4];
            float4 b1 = *(float4*)&Bs[kk][tx * 4 + 64];
            float a[8] = {a0.x, a0.y, a0.z, a0.w, a1.x, a1.y, a1.z, a1.w};
            float b[8] = {b0.x, b0.y, b0.z, b0.w, b1.x, b1.y, b1.z, b1.w};
#pragma unroll
            for (int i = 0; i < 8; i++)
#pragma unroll
                for (int j = 0; j < 8; j++) acc[i][j] += a[i] * b[j];
        }
        __syncthreads();
    }
#pragma unroll
    for (int ii = 0; ii < 2; ii++)
#pragma unroll
        for (int i = 0; i < 4; i++) {
            int row = m0 + ty * 4 + 64 * ii + i;
#pragma unroll
            for (int jj = 0; jj < 2; jj++) {
                float4 v = make_float4(acc[ii * 4 + i][jj * 4 + 0], acc[ii * 4 + i][jj * 4 + 1],
                                       acc[ii * 4 + i][jj * 4 + 2], acc[ii * 4 + i][jj * 4 + 3]);
                *(float4*)(out + (size_t)row * EE + col0 + tx * 4 + 64 * jj) = v;
            }
        }
}

// ---------------------------------------------------------------------------
// Logits: per (b,n,w) 128x128 tile of q_b @ k_{n-1+w}^T / 16.
// Out-of-range context block -> logits are literal zeros (matches zero-pad).
// grid (640, 3)
// ---------------------------------------------------------------------------
__global__ __launch_bounds__(256) void logits_kernel()
{
    const int tid = threadIdx.x;
    const int tx = tid & 15, ty = tid >> 4;
    const int bn = blockIdx.x;
    const int b = bn >> 5, n = bn & 31;
    const int w = blockIdx.y;
    const int j = n - 1 + w;
    float* Lbase = g_logits + (size_t)bn * (BLK * CTX) + w * 128;

    if (j < 0 || j >= NB) {
#pragma unroll
        for (int t = 0; t < 16; t++) {
            int f4 = tid + 256 * t;
            int row = f4 >> 5, c4 = f4 & 31;
            *(float4*)(Lbase + (size_t)row * CTX + c4 * 4) = make_float4(0.f, 0.f, 0.f, 0.f);
        }
        return;
    }

    __shared__ float As[16][128];
    __shared__ float Bs[16][128];
    const float* Abase = g_q + (size_t)(b * SS + n * 128) * EE;
    const float* Kbase = g_k + (size_t)(b * SS + j * 128) * EE;

    float acc[8][8];
#pragma unroll
    for (int i = 0; i < 8; i++)
#pragma unroll
        for (int jq = 0; jq < 8; jq++) acc[i][jq] = 0.f;

    for (int kt = 0; kt < EE; kt += 16) {
        // both operands transposed-load (NT gemm)
#pragma unroll
        for (int t = 0; t < 2; t++) {
            int f4 = tid + 256 * t;
            int row = f4 >> 2, c4 = f4 & 3;
            float4 va = *(const float4*)(Abase + (size_t)row * EE + kt + c4 * 4);
            As[c4 * 4 + 0][row] = va.x; As[c4 * 4 + 1][row] = va.y;
            As[c4 * 4 + 2][row] = va.z; As[c4 * 4 + 3][row] = va.w;
            float4 vb = *(const float4*)(Kbase + (size_t)row * EE + kt + c4 * 4);
            Bs[c4 * 4 + 0][row] = vb.x; Bs[c4 * 4 + 1][row] = vb.y;
            Bs[c4 * 4 + 2][row] = vb.z; Bs[c4 * 4 + 3][row] = vb.w;
        }
        __syncthreads();
#pragma unroll
        for (int kk = 0; kk < 16; kk++) {
            float4 a0 = *(float4*)&As[kk][ty * 4];
            float4 a1 = *(float4*)&As[kk][ty * 4 + 64];
            float4 b0 = *(float4*)&Bs[kk][tx * 4];
            float4 b1 = *(float4*)&Bs[kk][tx * 4 + 64];
            float a[8] = {a0.x, a0.y, a0.z, a0.w, a1.x, a1.y, a1.z, a1.w};
            float bq[8] = {b0.x, b0.y, b0.z, b0.w, b1.x, b1.y, b1.z, b1.w};
#pragma unroll
            for (int i = 0; i < 8; i++)
#pragma unroll
                for (int jq = 0; jq < 8; jq++) acc[i][jq] += a[i] * bq[jq];
        }
        __syncthreads();
    }
    const float scale = 0.0625f;  // 1/sqrt(256)
#pragma unroll
    for (int ii = 0; ii < 2; ii++)
#pragma unroll
        for (int i = 0; i < 4; i++) {
            int row = ty * 4 + 64 * ii + i;
#pragma unroll
            for (int jj = 0; jj < 2; jj++) {
                float4 v = make_float4(acc[ii * 4 + i][jj * 4 + 0] * scale,
                                       acc[ii * 4 + i][jj * 4 + 1] * scale,
                                       acc[ii * 4 + i][jj * 4 + 2] * scale,
                                       acc[ii * 4 + i][jj * 4 + 3] * scale);
                *(float4*)(Lbase + (size_t)row * CTX + tx * 4 + 64 * jj) = v;
            }
        }
}

// ---------------------------------------------------------------------------
// Softmax over 384, one warp per row (81920 rows).
// ---------------------------------------------------------------------------
__global__ __launch_bounds__(256) void softmax_kernel()
{
    const int gw = (blockIdx.x * blockDim.x + threadIdx.x) >> 5;
    const int lane = threadIdx.x & 31;
    float* row = g_logits + (size_t)gw * CTX;
    float v[12];
    float mx = -1e30f;
#pragma unroll
    for (int i = 0; i < 12; i++) { v[i] = row[lane + 32 * i]; mx = fmaxf(mx, v[i]); }
#pragma unroll
    for (int o = 16; o > 0; o >>= 1) mx = fmaxf(mx, __shfl_xor_sync(0xFFFFFFFFu, mx, o));
    float s = 0.f;
#pragma unroll
    for (int i = 0; i < 12; i++) { v[i] = __expf(v[i] - mx); s += v[i]; }
#pragma unroll
    for (int o = 16; o > 0; o >>= 1) s += __shfl_xor_sync(0xFFFFFFFFu, s, o);
    float inv = 1.f / s;
#pragma unroll
    for (int i = 0; i < 12; i++) row[lane + 32 * i] = v[i] * inv;
}

// ---------------------------------------------------------------------------
// AV: per (b,n): [128,384] @ vc[384,256]; out-of-range V rows read as zero.
// Output written at permuted row n*(B*128) + b*128 + q  (matches reference
// transpose(1,0,2,3).reshape).  grid (640, 2)
// ---------------------------------------------------------------------------
__global__ __launch_bounds__(256) void av_kernel()
{
    __shared__ float As[16][128];
    __shared__ float Bs[16][128];
    const int tid = threadIdx.x;
    const int tx = tid & 15, ty = tid >> 4;
    const int bn = blockIdx.x;
    const int b = bn >> 5, n = bn & 31;
    const int n0 = blockIdx.y * 128;
    const float* Abase = g_logits + (size_t)bn * (BLK * CTX);
    const int srow_base = (n - 1) * 128;

    float acc[8][8];
#pragma unroll
    for (int i = 0; i < 8; i++)
#pragma unroll
        for (int j = 0; j < 8; j++) acc[i][j] = 0.f;

    for (int kt = 0; kt < CTX; kt += 16) {
#pragma unroll
        for (int t = 0; t < 2; t++) {
            int f4 = tid + 256 * t;
            int row = f4 >> 2, c4 = f4 & 3;
            float4 v = *(const float4*)(Abase + (size_t)row * CTX + kt + c4 * 4);
            As[c4 * 4 + 0][row] = v.x; As[c4 * 4 + 1][row] = v.y;
            As[c4 * 4 + 2][row] = v.z; As[c4 * 4 + 3][row] = v.w;
        }
#pragma unroll
        for (int t = 0; t < 2; t++) {
            int f4 = tid + 256 * t;
            int row = f4 >> 5, c4 = f4 & 31;
            int sr = srow_base + kt + row;
            float4 v = make_float4(0.f, 0.f, 0.f, 0.f);
            if (sr >= 0 && sr < SS)
                v = *(const float4*)(g_v + (size_t)(b * SS + sr) * EE + n0 + c4 * 4);
            *(float4*)&Bs[row][c4 * 4] = v;
        }
        __syncthreads();
#pragma unroll
        for (int kk = 0; kk < 16; kk++) {
            float4 a0 = *(float4*)&As[kk][ty * 4];
            float4 a1 = *(float4*)&As[kk][ty * 4 + 64];
            float4 b0 = *(float4*)&Bs[kk][tx * 4];
            float4 b1 = *(float4*)&Bs[kk][tx * 4 + 64];
            float a[8] = {a0.x, a0.y, a0.z, a0.w, a1.x, a1.y, a1.z, a1.w};
            float bv[8] = {b0.x, b0.y, b0.z, b0.w, b1.x, b1.y, b1.z, b1.w};
#pragma unroll
            for (int i = 0; i < 8; i++)
#pragma unroll
                for (int j = 0; j < 8; j++) acc[i][j] += a[i] * bv[j];
        }
        __syncthreads();
    }
    const int orow_base = n * (BB * 128) + b * 128;
#pragma unroll
    for (int ii = 0; ii < 2; ii++)
#pragma unroll
        for (int i = 0; i < 4; i++) {
            int row = orow_base + ty * 4 + 64 * ii + i;
#pragma unroll
            for (int jj = 0; jj < 2; jj++) {
                float4 v = make_float4(acc[ii * 4 + i][jj * 4 + 0], acc[ii * 4 + i][jj * 4 + 1],
                                       acc[ii * 4 + i][jj * 4 + 2], acc[ii * 4 + i][jj * 4 + 3]);
                *(float4*)(g_att + (size_t)row * EE + n0 + tx * 4 + 64 * jj) = v;
            }
        }
}

// ---------------------------------------------------------------------------
// Output projection: [81920,256] @ Wo[256,256] + bo -> d_out.  grid (640, 2)
// ---------------------------------------------------------------------------
__global__ __launch_bounds__(256) void out_kernel(const float* __restrict__ Wo,
                                                  const float* __restrict__ bo,
                                                  float* __restrict__ out)
{
    __shared__ float As[16][128];
    __shared__ float Bs[16][128];
    const int tid = threadIdx.x;
    const int tx = tid & 15, ty = tid >> 4;
    const int m0 = blockIdx.x * 128;
    const int n0 = blockIdx.y * 128;

    float acc[8][8];
#pragma unroll
    for (int i = 0; i < 8; i++)
#pragma unroll
        for (int j = 0; j < 8; j++) acc[i][j] = 0.f;

    for (int kt = 0; kt < EE; kt += 16) {
#pragma unroll
        for (int t = 0; t < 2; t++) {
            int f4 = tid + 256 * t;
            int row = f4 >> 2, c4 = f4 & 3;
            float4 v = *(const float4*)(g_att + (size_t)(m0 + row) * EE + kt + c4 * 4);
            As[c4 * 4 + 0][row] = v.x; As[c4 * 4 + 1][row] = v.y;
            As[c4 * 4 + 2][row] = v.z; As[c4 * 4 + 3][row] = v.w;
        }
#pragma unroll
        for (int t = 0; t < 2; t++) {
            int f4 = tid + 256 * t;
            int row = f4 >> 5, c4 = f4 & 31;
            float4 v = *(const float4*)(Wo + (size_t)(kt + row) * EE + n0 + c4 * 4);
            *(float4*)&Bs[row][c4 * 4] = v;
        }
        __syncthreads();
#pragma unroll
        for (int kk = 0; kk < 16; kk++) {
            float4 a0 = *(float4*)&As[kk][ty * 4];
            float4 a1 = *(float4*)&As[kk][ty * 4 + 64];
            float4 b0 = *(float4*)&Bs[kk][tx * 4];
            float4 b1 = *(float4*)&Bs[kk][tx * 4 + 64];
            float a[8] = {a0.x, a0.y, a0.z, a0.w, a1.x, a1.y, a1.z, a1.w};
            float bw[8] = {b0.x, b0.y, b0.z, b0.w, b1.x, b1.y, b1.z, b1.w};
#pragma unroll
            for (int i = 0; i < 8; i++)
#pragma unroll
                for (int j = 0; j < 8; j++) acc[i][j] += a[i] * bw[j];
        }
        __syncthreads();
    }
    float4 bias0 = *(const float4*)(bo + n0 + tx * 4);
    float4 bias1 = *(const float4*)(bo + n0 + tx * 4 + 64);
#pragma unroll
    for (int ii = 0; ii < 2; ii++)
#pragma unroll
        for (int i = 0; i < 4; i++) {
            int row = m0 + ty * 4 + 64 * ii + i;
            float4 v0 = make_float4(acc[ii * 4 + i][0] + bias0.x, acc[ii * 4 + i][1] + bias0.y,
                                    acc[ii * 4 + i][2] + bias0.z, acc[ii * 4 + i][3] + bias0.w);
            float4 v1 = make_float4(acc[ii * 4 + i][4] + bias1.x, acc[ii * 4 + i][5] + bias1.y,
                                    acc[ii * 4 + i][6] + bias1.z, acc[ii * 4 + i][7] + bias1.w);
            *(float4*)(out + (size_t)row * EE + n0 + tx * 4) = v0;
            *(float4*)(out + (size_t)row * EE + n0 + tx * 4 + 64) = v1;
        }
}

extern "C" void kernel_launch(void* const* d_in, const int* in_sizes, int n_in,
                              void* d_out, int out_size)
{
    const float* x  = (const float*)d_in[0];
    const float* Wq = (const float*)d_in[1];
    const float* Wk = (const float*)d_in[2];
    const float* Wv = (const float*)d_in[3];
    const float* Wo = (const float*)d_in[4];
    const float* bo = (const float*)d_in[5];
    float* out = (float*)d_out;

    qkv_kernel<<<dim3(640, 6), 256>>>(x, Wq, Wk, Wv);
    logits_kernel<<<dim3(640, 3), 256>>>();
    softmax_kernel<<<dim3(10240), 256>>>();
    av_kernel<<<dim3(640, 2), 256>>>();
    out_kernel<<<dim3(640, 2), 256>>>(Wo, bo, out);
}

// round 13
// speedup vs baseline: 1.7124x; 1.7110x over previous
#include <cuda_runtime.h>
#include <cuda_bf16.h>
#include <cstdint>

#define BB 20
#define SS 4096
#define EE 256
#define NB 32
#define BLK 128
#define CTX 384

// SMEM padded row stride in bytes (32 bf16 = 64B data + 16B pad)
#define SSTRIDE 80

// ---------------- device scratch ----------------
__device__ float g_q[(size_t)BB * SS * EE];              // (x@Wq)/16
__device__ float g_k[(size_t)BB * SS * EE];
__device__ float g_vT[(size_t)BB * EE * SS];             // v transposed [b][e][seq]
__device__ float g_att[(size_t)BB * SS * EE];            // permuted attn output
__device__ float g_logits[(size_t)BB * NB * BLK * CTX];  // logits -> probs (in-place softmax)
__device__ __nv_bfloat16 g_wth[4][EE * EE];              // W^T hi (0:Wq/16 1:Wk 2:Wv 3:Wo)
__device__ __nv_bfloat16 g_wtl[4][EE * EE];              // W^T lo

// ---------------- PTX primitives (baseline PTX, sm_80-class) ----------------
static __device__ __forceinline__ uint32_t smem_u32(const void* p) {
    return (uint32_t)__cvta_generic_to_shared(p);
}
static __device__ __forceinline__ void ldsm4(uint32_t& r0, uint32_t& r1, uint32_t& r2,
                                             uint32_t& r3, uint32_t addr) {
    asm volatile("ldmatrix.sync.aligned.m8n8.x4.shared.b16 {%0,%1,%2,%3}, [%4];"
                 : "=r"(r0), "=r"(r1), "=r"(r2), "=r"(r3) : "r"(addr));
}
static __device__ __forceinline__ void mma16816(float* c, const uint32_t* a, const uint32_t* b) {
    asm volatile(
        "mma.sync.aligned.m16n8k16.row.col.f32.bf16.bf16.f32 "
        "{%0,%1,%2,%3}, {%4,%5,%6,%7}, {%8,%9}, {%0,%1,%2,%3};"
        : "+f"(c[0]), "+f"(c[1]), "+f"(c[2]), "+f"(c[3])
        : "r"(a[0]), "r"(a[1]), "r"(a[2]), "r"(a[3]), "r"(b[0]), "r"(b[1]));
}

// ---------------- SMEM fill: fp32 -> bf16 hi/lo (128 rows x 32 cols) ----------------
static __device__ __forceinline__ void load_cvt32(const float* __restrict__ src, int lda,
                                                  char* shi, char* slo, int tid) {
#pragma unroll
    for (int i = 0; i < 4; i++) {
        int f = tid + 256 * i;
        int row = f >> 3, c4 = f & 7;
        float4 v = *(const float4*)(src + (size_t)row * lda + c4 * 4);
        __nv_bfloat162 ha = __floats2bfloat162_rn(v.x, v.y);
        __nv_bfloat162 hb = __floats2bfloat162_rn(v.z, v.w);
        float2 fa = __bfloat1622float2(ha);
        float2 fb = __bfloat1622float2(hb);
        __nv_bfloat162 la = __floats2bfloat162_rn(v.x - fa.x, v.y - fa.y);
        __nv_bfloat162 lb = __floats2bfloat162_rn(v.z - fb.x, v.w - fb.y);
        int off = row * SSTRIDE + c4 * 8;
        *(uint2*)(shi + off) = make_uint2(*(uint32_t*)&ha, *(uint32_t*)&hb);
        *(uint2*)(slo + off) = make_uint2(*(uint32_t*)&la, *(uint32_t*)&lb);
    }
}
// Preconverted bf16 weights: copy 128 rows x 32 cols (src row stride EE)
static __device__ __forceinline__ void load_wcopy(const __nv_bfloat16* __restrict__ wh,
                                                  const __nv_bfloat16* __restrict__ wl,
                                                  char* shi, char* slo, int tid) {
#pragma unroll
    for (int i = 0; i < 2; i++) {
        int f = tid + 256 * i;
        int row = f >> 2, c = f & 3;
        int off = row * SSTRIDE + c * 16;
        *(uint4*)(shi + off) = *(const uint4*)(wh + (size_t)row * EE + c * 8);
        *(uint4*)(slo + off) = *(const uint4*)(wl + (size_t)row * EE + c * 8);
    }
}

// ---------------- one 32-k chunk of bf16x3 MMAs ----------------
static __device__ __forceinline__ void mma_chunk(uint32_t uAh, uint32_t uAl, uint32_t uBh,
                                                 uint32_t uBl, int lane, int m_warp, int n_warp,
                                                 float c[2][8][4]) {
#pragma unroll
    for (int kk = 0; kk < 2; kk++) {
        const int kb = kk * 32;
        uint32_t ah[2][4], al[2][4], bh[8][2], bl[8][2];
        const uint32_t a_off =
            (uint32_t)((m_warp + (lane & 15)) * SSTRIDE + kb + ((lane >> 4) << 4));
        ldsm4(ah[0][0], ah[0][1], ah[0][2], ah[0][3], uAh + a_off);
        ldsm4(ah[1][0], ah[1][1], ah[1][2], ah[1][3], uAh + a_off + 16 * SSTRIDE);
        ldsm4(al[0][0], al[0][1], al[0][2], al[0][3], uAl + a_off);
        ldsm4(al[1][0], al[1][1], al[1][2], al[1][3], uAl + a_off + 16 * SSTRIDE);
        const int br = (lane & 7) + ((lane >> 4) << 3);
        const int bc = kb + (((lane >> 3) & 1) << 4);
#pragma unroll
        for (int j = 0; j < 4; j++) {
            const uint32_t b_off = (uint32_t)((n_warp + 16 * j + br) * SSTRIDE + bc);
            uint32_t r0, r1, r2, r3;
            ldsm4(r0, r1, r2, r3, uBh + b_off);
            bh[2 * j][0] = r0; bh[2 * j][1] = r1;
            bh[2 * j + 1][0] = r2; bh[2 * j + 1][1] = r3;
            ldsm4(r0, r1, r2, r3, uBl + b_off);
            bl[2 * j][0] = r0; bl[2 * j][1] = r1;
            bl[2 * j + 1][0] = r2; bl[2 * j + 1][1] = r3;
        }
#pragma unroll
        for (int mi = 0; mi < 2; mi++)
#pragma unroll
            for (int nj = 0; nj < 8; nj++) {
                mma16816(c[mi][nj], ah[mi], bh[nj]);
                mma16816(c[mi][nj], ah[mi], bl[nj]);
                mma16816(c[mi][nj], al[mi], bh[nj]);
            }
    }
}

// ---------------- weight prep: W^T bf16 hi/lo (Wq prescaled by 1/16) ----------------
__global__ __launch_bounds__(256) void prep_w(const float* __restrict__ Wq,
                                              const float* __restrict__ Wk,
                                              const float* __restrict__ Wv,
                                              const float* __restrict__ Wo) {
    int idx = blockIdx.x * 256 + threadIdx.x;
    int mat = idx >> 16;
    int e = idx & 65535;
    int n = e & 255, k = e >> 8;
    const float* W = (mat == 0) ? Wq : (mat == 1) ? Wk : (mat == 2) ? Wv : Wo;
    float w = W[k * 256 + n] * ((mat == 0) ? 0.0625f : 1.0f);
    __nv_bfloat16 h = __float2bfloat16_rn(w);
    g_wth[mat][n * 256 + k] = h;
    g_wtl[mat][n * 256 + k] = __float2bfloat16_rn(w - __bfloat162float(h));
}

// ---------------- QKV: x @ {Wq/16,Wk,Wv}.  grid (640, 6) ----------------
__global__ __launch_bounds__(256) void qkv_mma(const float* __restrict__ x) {
    __shared__ __align__(16) char sAh[128 * SSTRIDE], sAl[128 * SSTRIDE];
    __shared__ __align__(16) char sBh[128 * SSTRIDE], sBl[128 * SSTRIDE];
    const int tid = threadIdx.x, lane = tid & 31, wid = tid >> 5;
    const int m_warp = (wid >> 1) * 32, n_warp = (wid & 1) * 64;
    const int m0 = blockIdx.x * 128;
    const int sel = blockIdx.y >> 1, nh = blockIdx.y & 1;
    const __nv_bfloat16* wh = g_wth[sel] + (size_t)nh * 128 * EE;
    const __nv_bfloat16* wl = g_wtl[sel] + (size_t)nh * 128 * EE;
    const uint32_t uAh = smem_u32(sAh), uAl = smem_u32(sAl);
    const uint32_t uBh = smem_u32(sBh), uBl = smem_u32(sBl);

    float c[2][8][4];
#pragma unroll
    for (int i = 0; i < 2; i++)
#pragma unroll
        for (int j = 0; j < 8; j++)
#pragma unroll
            for (int t = 0; t < 4; t++) c[i][j][t] = 0.f;

    for (int kc = 0; kc < 8; kc++) {
        load_cvt32(x + (size_t)m0 * EE + kc * 32, EE, sAh, sAl, tid);
        load_wcopy(wh + kc * 32, wl + kc * 32, sBh, sBl, tid);
        __syncthreads();
        mma_chunk(uAh, uAl, uBh, uBl, lane, m_warp, n_warp, c);
        __syncthreads();
    }

    if (sel < 2) {
        float* dst = (sel == 0) ? g_q : g_k;
#pragma unroll
        for (int mi = 0; mi < 2; mi++)
#pragma unroll
            for (int nj = 0; nj < 8; nj++) {
                int r = m0 + m_warp + mi * 16 + (lane >> 2);
                int col = nh * 128 + n_warp + nj * 8 + (lane & 3) * 2;
                *(float2*)(dst + (size_t)r * EE + col) = make_float2(c[mi][nj][0], c[mi][nj][1]);
                *(float2*)(dst + (size_t)(r + 8) * EE + col) =
                    make_float2(c[mi][nj][2], c[mi][nj][3]);
            }
    } else {
#pragma unroll
        for (int mi = 0; mi < 2; mi++)
#pragma unroll
            for (int nj = 0; nj < 8; nj++) {
                int r = m0 + m_warp + mi * 16 + (lane >> 2);
                int col = nh * 128 + n_warp + nj * 8 + (lane & 3) * 2;
                int b0 = r >> 12, s0 = r & 4095;
                int b1 = (r + 8) >> 12, s1 = (r + 8) & 4095;
                g_vT[(size_t)b0 * EE * SS + (size_t)col * SS + s0] = c[mi][nj][0];
                g_vT[(size_t)b0 * EE * SS + (size_t)(col + 1) * SS + s0] = c[mi][nj][1];
                g_vT[(size_t)b1 * EE * SS + (size_t)col * SS + s1] = c[mi][nj][2];
                g_vT[(size_t)b1 * EE * SS + (size_t)(col + 1) * SS + s1] = c[mi][nj][3];
            }
    }
}

// ---------------- logits: (q/16) @ k^T per (b,n,w).  grid (640, 3) ----------------
__global__ __launch_bounds__(256) void logits_mma() {
    const int tid = threadIdx.x, lane = tid & 31, wid = tid >> 5;
    const int bn = blockIdx.x;
    const int b = bn >> 5, n = bn & 31;
    const int w = blockIdx.y;
    const int j = n - 1 + w;
    float* Lbase = g_logits + (size_t)bn * (BLK * CTX) + w * 128;

    if (j < 0 || j >= NB) {
#pragma unroll
        for (int t = 0; t < 16; t++) {
            int f4 = tid + 256 * t;
            int row = f4 >> 5, c4 = f4 & 31;
            *(float4*)(Lbase + (size_t)row * CTX + c4 * 4) = make_float4(0.f, 0.f, 0.f, 0.f);
        }
        return;
    }

    __shared__ __align__(16) char sAh[128 * SSTRIDE], sAl[128 * SSTRIDE];
    __shared__ __align__(16) char sBh[128 * SSTRIDE], sBl[128 * SSTRIDE];
    const int m_warp = (wid >> 1) * 32, n_warp = (wid & 1) * 64;
    const uint32_t uAh = smem_u32(sAh), uAl = smem_u32(sAl);
    const uint32_t uBh = smem_u32(sBh), uBl = smem_u32(sBl);
    const float* qsrc = g_q + (size_t)(b * SS + n * 128) * EE;
    const float* ksrc = g_k + (size_t)(b * SS + j * 128) * EE;

    float c[2][8][4];
#pragma unroll
    for (int i = 0; i < 2; i++)
#pragma unroll
        for (int jq = 0; jq < 8; jq++)
#pragma unroll
            for (int t = 0; t < 4; t++) c[i][jq][t] = 0.f;

    for (int kc = 0; kc < 8; kc++) {
        load_cvt32(qsrc + kc * 32, EE, sAh, sAl, tid);
        load_cvt32(ksrc + kc * 32, EE, sBh, sBl, tid);
        __syncthreads();
        mma_chunk(uAh, uAl, uBh, uBl, lane, m_warp, n_warp, c);
        __syncthreads();
    }
#pragma unroll
    for (int mi = 0; mi < 2; mi++)
#pragma unroll
        for (int nj = 0; nj < 8; nj++) {
            int r = m_warp + mi * 16 + (lane >> 2);
            int col = n_warp + nj * 8 + (lane & 3) * 2;
            *(float2*)(Lbase + (size_t)r * CTX + col) = make_float2(c[mi][nj][0], c[mi][nj][1]);
            *(float2*)(Lbase + (size_t)(r + 8) * CTX + col) =
                make_float2(c[mi][nj][2], c[mi][nj][3]);
        }
}

// ---------------- softmax over 384, one warp per row (proven) ----------------
__global__ __launch_bounds__(256) void softmax_kernel() {
    const int gw = (blockIdx.x * blockDim.x + threadIdx.x) >> 5;
    const int lane = threadIdx.x & 31;
    float* row = g_logits + (size_t)gw * CTX;
    float v[12];
    float mx = -1e30f;
#pragma unroll
    for (int i = 0; i < 12; i++) { v[i] = row[lane + 32 * i]; mx = fmaxf(mx, v[i]); }
#pragma unroll
    for (int o = 16; o > 0; o >>= 1) mx = fmaxf(mx, __shfl_xor_sync(0xFFFFFFFFu, mx, o));
    float s = 0.f;
#pragma unroll
    for (int i = 0; i < 12; i++) { v[i] = __expf(v[i] - mx); s += v[i]; }
#pragma unroll
    for (int o = 16; o > 0; o >>= 1) s += __shfl_xor_sync(0xFFFFFFFFu, s, o);
    float inv = 1.f / s;
#pragma unroll
    for (int i = 0; i < 12; i++) row[lane + 32 * i] = v[i] * inv;
}

// ---------------- AV: probs[128,384] @ vT^T, permuted output.  grid (640, 2) ----------------
__global__ __launch_bounds__(256) void av_mma() {
    __shared__ __align__(16) char sAh[128 * SSTRIDE], sAl[128 * SSTRIDE];
    __shared__ __align__(16) char sBh[128 * SSTRIDE], sBl[128 * SSTRIDE];
    const int tid = threadIdx.x, lane = tid & 31, wid = tid >> 5;
    const int m_warp = (wid >> 1) * 32, n_warp = (wid & 1) * 64;
    const int bn = blockIdx.x;
    const int b = bn >> 5, n = bn & 31;
    const int n0 = blockIdx.y * 128;
    const uint32_t uAh = smem_u32(sAh), uAl = smem_u32(sAl);
    const uint32_t uBh = smem_u32(sBh), uBl = smem_u32(sBl);
    const float* psrc = g_logits + (size_t)bn * (BLK * CTX);
    const float* vsrc = g_vT + (size_t)b * EE * SS + (size_t)n0 * SS;

    float c[2][8][4];
#pragma unroll
    for (int i = 0; i < 2; i++)
#pragma unroll
        for (int jq = 0; jq < 8; jq++)
#pragma unroll
            for (int t = 0; t < 4; t++) c[i][jq][t] = 0.f;

    for (int kc = 0; kc < 12; kc++) {
        int key0 = (n - 1) * 128 + kc * 32;
        if (key0 < 0 || key0 >= SS) continue;  // padded region: v == 0
        load_cvt32(psrc + kc * 32, CTX, sAh, sAl, tid);
        load_cvt32(vsrc + key0, SS, sBh, sBl, tid);
        __syncthreads();
        mma_chunk(uAh, uAl, uBh, uBl, lane, m_warp, n_warp, c);
        __syncthreads();
    }
    const int orow_base = n * (BB * 128) + b * 128;
#pragma unroll
    for (int mi = 0; mi < 2; mi++)
#pragma unroll
        for (int nj = 0; nj < 8; nj++) {
            int r = orow_base + m_warp + mi * 16 + (lane >> 2);
            int col = n0 + n_warp + nj * 8 + (lane & 3) * 2;
            *(float2*)(g_att + (size_t)r * EE + col) = make_float2(c[mi][nj][0], c[mi][nj][1]);
            *(float2*)(g_att + (size_t)(r + 8) * EE + col) =
                make_float2(c[mi][nj][2], c[mi][nj][3]);
        }
}

// ---------------- out-proj: att @ Wo + bo.  grid (640, 2) ----------------
__global__ __launch_bounds__(256) void out_mma(const float* __restrict__ bo,
                                               float* __restrict__ out) {
    __shared__ __align__(16) char sAh[128 * SSTRIDE], sAl[128 * SSTRIDE];
    __shared__ __align__(16) char sBh[128 * SSTRIDE], sBl[128 * SSTRIDE];
    const int tid = threadIdx.x, lane = tid & 31, wid = tid >> 5;
    const int m_warp = (wid >> 1) * 32, n_warp = (wid & 1) * 64;
    const int m0 = blockIdx.x * 128;
    const int n0 = blockIdx.y * 128;
    const __nv_bfloat16* wh = g_wth[3] + (size_t)n0 * EE;
    const __nv_bfloat16* wl = g_wtl[3] + (size_t)n0 * EE;
    const uint32_t uAh = smem_u32(sAh), uAl = smem_u32(sAl);
    const uint32_t uBh = smem_u32(sBh), uBl = smem_u32(sBl);

    float c[2][8][4];
#pragma unroll
    for (int i = 0; i < 2; i++)
#pragma unroll
        for (int jq = 0; jq < 8; jq++)
#pragma unroll
            for (int t = 0; t < 4; t++) c[i][jq][t] = 0.f;

    for (int kc = 0; kc < 8; kc++) {
        load_cvt32(g_att + (size_t)m0 * EE + kc * 32, EE, sAh, sAl, tid);
        load_wcopy(wh + kc * 32, wl + kc * 32, sBh, sBl, tid);
        __syncthreads();
        mma_chunk(uAh, uAl, uBh, uBl, lane, m_warp, n_warp, c);
        __syncthreads();
    }
#pragma unroll
    for (int mi = 0; mi < 2; mi++)
#pragma unroll
        for (int nj = 0; nj < 8; nj++) {
            int r = m0 + m_warp + mi * 16 + (lane >> 2);
            int col = n0 + n_warp + nj * 8 + (lane & 3) * 2;
            float2 bv = *(const float2*)(bo + col);
            *(float2*)(out + (size_t)r * EE + col) =
                make_float2(c[mi][nj][0] + bv.x, c[mi][nj][1] + bv.y);
            *(float2*)(out + (size_t)(r + 8) * EE + col) =
                make_float2(c[mi][nj][2] + bv.x, c[mi][nj][3] + bv.y);
        }
}

// ---------------- launch ----------------
extern "C" void kernel_launch(void* const* d_in, const int* in_sizes, int n_in,
                              void* d_out, int out_size) {
    const float* x  = (const float*)d_in[0];
    const float* Wq = (const float*)d_in[1];
    const float* Wk = (const float*)d_in[2];
    const float* Wv = (const float*)d_in[3];
    const float* Wo = (const float*)d_in[4];
    const float* bo = (const float*)d_in[5];
    float* out = (float*)d_out;

    prep_w<<<1024, 256>>>(Wq, Wk, Wv, Wo);
    qkv_mma<<<dim3(640, 6), 256>>>(x);
    logits_mma<<<dim3(640, 3), 256>>>();
    softmax_kernel<<<10240, 256>>>();
    av_mma<<<dim3(640, 2), 256>>>();
    out_mma<<<dim3(640, 2), 256>>>(bo, out);
}

// round 14
// speedup vs baseline: 1.9659x; 1.1480x over previous
#include <cuda_runtime.h>
#include <cuda_bf16.h>
#include <cstdint>

#define BB 20
#define SS 4096
#define EE 256
#define NB 32
#define BLK 128
#define CTX 384

// SMEM padded row stride in bytes (32 bf16 = 64B data + 16B pad, 16B-aligned rows)
#define SSTRIDE 80
// one buffer = Ah | Al | Bh | Bl, each 128*SSTRIDE = 10240 B
#define BUF_AH 0
#define BUF_AL 10240
#define BUF_BH 20480
#define BUF_BL 30720
#define BUF_SZ 40960
#define SMEM_PIPE (2 * BUF_SZ)  // 81920 B dynamic

// ---------------- device scratch ----------------
__device__ float g_q[(size_t)BB * SS * EE];              // (x@Wq)/16
__device__ float g_k[(size_t)BB * SS * EE];
__device__ float g_vT[(size_t)BB * EE * SS];             // v transposed [b][e][seq]
__device__ float g_att[(size_t)BB * SS * EE];            // permuted attn output
__device__ float g_probs[(size_t)BB * NB * BLK * CTX];   // exp(logits), unnormalized
__device__ float g_rinv[BB * NB * BLK];                  // 1/rowsum
__device__ __nv_bfloat16 g_wth[4][EE * EE];              // W^T hi (0:Wq/16 1:Wk 2:Wv 3:Wo)
__device__ __nv_bfloat16 g_wtl[4][EE * EE];              // W^T lo

// ---------------- PTX primitives ----------------
static __device__ __forceinline__ uint32_t smem_u32(const void* p) {
    return (uint32_t)__cvta_generic_to_shared(p);
}
static __device__ __forceinline__ void ldsm4(uint32_t& r0, uint32_t& r1, uint32_t& r2,
                                             uint32_t& r3, uint32_t addr) {
    asm volatile("ldmatrix.sync.aligned.m8n8.x4.shared.b16 {%0,%1,%2,%3}, [%4];"
                 : "=r"(r0), "=r"(r1), "=r"(r2), "=r"(r3) : "r"(addr));
}
static __device__ __forceinline__ void mma16816(float* c, const uint32_t* a, const uint32_t* b) {
    asm volatile(
        "mma.sync.aligned.m16n8k16.row.col.f32.bf16.bf16.f32 "
        "{%0,%1,%2,%3}, {%4,%5,%6,%7}, {%8,%9}, {%0,%1,%2,%3};"
        : "+f"(c[0]), "+f"(c[1]), "+f"(c[2]), "+f"(c[3])
        : "r"(a[0]), "r"(a[1]), "r"(a[2]), "r"(a[3]), "r"(b[0]), "r"(b[1]));
}

// ---------------- register staging: LDG early, convert+STS late ----------------
struct StageCvt { float4 v[4]; };
static __device__ __forceinline__ void ldg_cvt(StageCvt& st, const float* __restrict__ src,
                                               int lda, int tid) {
#pragma unroll
    for (int i = 0; i < 4; i++) {
        int f = tid + 256 * i;
        int row = f >> 3, c4 = f & 7;
        st.v[i] = *(const float4*)(src + (size_t)row * lda + c4 * 4);
    }
}
static __device__ __forceinline__ void sts_cvt(const StageCvt& st, char* shi, char* slo,
                                               int tid) {
#pragma unroll
    for (int i = 0; i < 4; i++) {
        int f = tid + 256 * i;
        int row = f >> 3, c4 = f & 7;
        float4 v = st.v[i];
        __nv_bfloat162 ha = __floats2bfloat162_rn(v.x, v.y);
        __nv_bfloat162 hb = __floats2bfloat162_rn(v.z, v.w);
        float2 fa = __bfloat1622float2(ha);
        float2 fb = __bfloat1622float2(hb);
        __nv_bfloat162 la = __floats2bfloat162_rn(v.x - fa.x, v.y - fa.y);
        __nv_bfloat162 lb = __floats2bfloat162_rn(v.z - fb.x, v.w - fb.y);
        int off = row * SSTRIDE + c4 * 8;
        *(uint2*)(shi + off) = make_uint2(*(uint32_t*)&ha, *(uint32_t*)&hb);
        *(uint2*)(slo + off) = make_uint2(*(uint32_t*)&la, *(uint32_t*)&lb);
    }
}
struct StageW { uint4 v[2][2]; };  // [i][0]=hi [i][1]=lo
static __device__ __forceinline__ void ldg_w(StageW& st, const __nv_bfloat16* __restrict__ wh,
                                             const __nv_bfloat16* __restrict__ wl, int tid) {
#pragma unroll
    for (int i = 0; i < 2; i++) {
        int f = tid + 256 * i;
        int row = f >> 2, c = f & 3;
        st.v[i][0] = *(const uint4*)(wh + (size_t)row * EE + c * 8);
        st.v[i][1] = *(const uint4*)(wl + (size_t)row * EE + c * 8);
    }
}
static __device__ __forceinline__ void sts_w(const StageW& st, char* shi, char* slo, int tid) {
#pragma unroll
    for (int i = 0; i < 2; i++) {
        int f = tid + 256 * i;
        int row = f >> 2, c = f & 3;
        int off = row * SSTRIDE + c * 16;
        *(uint4*)(shi + off) = st.v[i][0];
        *(uint4*)(slo + off) = st.v[i][1];
    }
}

// ---------------- one 32-k chunk of bf16x3 MMAs from buffer `base` ----------------
static __device__ __forceinline__ void mma_chunk(uint32_t base, int lane, int m_warp,
                                                 int n_warp, float c[2][8][4]) {
    const uint32_t uAh = base + BUF_AH, uAl = base + BUF_AL;
    const uint32_t uBh = base + BUF_BH, uBl = base + BUF_BL;
#pragma unroll
    for (int kk = 0; kk < 2; kk++) {
        const int kb = kk * 32;
        uint32_t ah[2][4], al[2][4], bh[8][2], bl[8][2];
        const uint32_t a_off =
            (uint32_t)((m_warp + (lane & 15)) * SSTRIDE + kb + ((lane >> 4) << 4));
        ldsm4(ah[0][0], ah[0][1], ah[0][2], ah[0][3], uAh + a_off);
        ldsm4(ah[1][0], ah[1][1], ah[1][2], ah[1][3], uAh + a_off + 16 * SSTRIDE);
        ldsm4(al[0][0], al[0][1], al[0][2], al[0][3], uAl + a_off);
        ldsm4(al[1][0], al[1][1], al[1][2], al[1][3], uAl + a_off + 16 * SSTRIDE);
        const int br = (lane & 7) + ((lane >> 4) << 3);
        const int bc = kb + (((lane >> 3) & 1) << 4);
#pragma unroll
        for (int j = 0; j < 4; j++) {
            const uint32_t b_off = (uint32_t)((n_warp + 16 * j + br) * SSTRIDE + bc);
            uint32_t r0, r1, r2, r3;
            ldsm4(r0, r1, r2, r3, uBh + b_off);
            bh[2 * j][0] = r0; bh[2 * j][1] = r1;
            bh[2 * j + 1][0] = r2; bh[2 * j + 1][1] = r3;
            ldsm4(r0, r1, r2, r3, uBl + b_off);
            bl[2 * j][0] = r0; bl[2 * j][1] = r1;
            bl[2 * j + 1][0] = r2; bl[2 * j + 1][1] = r3;
        }
#pragma unroll
        for (int mi = 0; mi < 2; mi++)
#pragma unroll
            for (int nj = 0; nj < 8; nj++) {
                mma16816(c[mi][nj], ah[mi], bh[nj]);
                mma16816(c[mi][nj], ah[mi], bl[nj]);
                mma16816(c[mi][nj], al[mi], bh[nj]);
            }
    }
}

// ---------------- weight prep: W^T bf16 hi/lo (Wq prescaled by 1/16) ----------------
__global__ __launch_bounds__(256) void prep_w(const float* __restrict__ Wq,
                                              const float* __restrict__ Wk,
                                              const float* __restrict__ Wv,
                                              const float* __restrict__ Wo) {
    int idx = blockIdx.x * 256 + threadIdx.x;
    int mat = idx >> 16;
    int e = idx & 65535;
    int n = e & 255, k = e >> 8;
    const float* W = (mat == 0) ? Wq : (mat == 1) ? Wk : (mat == 2) ? Wv : Wo;
    float w = W[k * 256 + n] * ((mat == 0) ? 0.0625f : 1.0f);
    __nv_bfloat16 h = __float2bfloat16_rn(w);
    g_wth[mat][n * 256 + k] = h;
    g_wtl[mat][n * 256 + k] = __float2bfloat16_rn(w - __bfloat162float(h));
}

// ---------------- QKV: x @ {Wq/16,Wk,Wv}.  grid (640, 6) ----------------
__global__ __launch_bounds__(256) void qkv_mma(const float* __restrict__ x) {
    extern __shared__ __align__(16) char dsm[];
    const int tid = threadIdx.x, lane = tid & 31, wid = tid >> 5;
    const int m_warp = (wid >> 1) * 32, n_warp = (wid & 1) * 64;
    const int m0 = blockIdx.x * 128;
    const int sel = blockIdx.y >> 1, nh = blockIdx.y & 1;
    const __nv_bfloat16* wh = g_wth[sel] + (size_t)nh * 128 * EE;
    const __nv_bfloat16* wl = g_wtl[sel] + (size_t)nh * 128 * EE;
    const float* asrc = x + (size_t)m0 * EE;
    char* buf[2] = {dsm, dsm + BUF_SZ};
    const uint32_t ub[2] = {smem_u32(buf[0]), smem_u32(buf[1])};

    float c[2][8][4];
#pragma unroll
    for (int i = 0; i < 2; i++)
#pragma unroll
        for (int j = 0; j < 8; j++)
#pragma unroll
            for (int t = 0; t < 4; t++) c[i][j][t] = 0.f;

    StageCvt sa; StageW sw;
    ldg_cvt(sa, asrc, EE, tid);
    ldg_w(sw, wh, wl, tid);
    sts_cvt(sa, buf[0] + BUF_AH, buf[0] + BUF_AL, tid);
    sts_w(sw, buf[0] + BUF_BH, buf[0] + BUF_BL, tid);
    __syncthreads();
    for (int kc = 0; kc < 8; kc++) {
        int cur = kc & 1, nxt = cur ^ 1;
        if (kc < 7) {
            ldg_cvt(sa, asrc + (kc + 1) * 32, EE, tid);
            ldg_w(sw, wh + (kc + 1) * 32, wl + (kc + 1) * 32, tid);
        }
        mma_chunk(ub[cur], lane, m_warp, n_warp, c);
        if (kc < 7) {
            sts_cvt(sa, buf[nxt] + BUF_AH, buf[nxt] + BUF_AL, tid);
            sts_w(sw, buf[nxt] + BUF_BH, buf[nxt] + BUF_BL, tid);
        }
        __syncthreads();
    }

    if (sel < 2) {
        float* dst = (sel == 0) ? g_q : g_k;
#pragma unroll
        for (int mi = 0; mi < 2; mi++)
#pragma unroll
            for (int nj = 0; nj < 8; nj++) {
                int r = m0 + m_warp + mi * 16 + (lane >> 2);
                int col = nh * 128 + n_warp + nj * 8 + (lane & 3) * 2;
                *(float2*)(dst + (size_t)r * EE + col) = make_float2(c[mi][nj][0], c[mi][nj][1]);
                *(float2*)(dst + (size_t)(r + 8) * EE + col) =
                    make_float2(c[mi][nj][2], c[mi][nj][3]);
            }
    } else {
#pragma unroll
        for (int mi = 0; mi < 2; mi++)
#pragma unroll
            for (int nj = 0; nj < 8; nj++) {
                int r = m0 + m_warp + mi * 16 + (lane >> 2);
                int col = nh * 128 + n_warp + nj * 8 + (lane & 3) * 2;
                int b0 = r >> 12, s0 = r & 4095;
                int b1 = (r + 8) >> 12, s1 = (r + 8) & 4095;
                g_vT[(size_t)b0 * EE * SS + (size_t)col * SS + s0] = c[mi][nj][0];
                g_vT[(size_t)b0 * EE * SS + (size_t)(col + 1) * SS + s0] = c[mi][nj][1];
                g_vT[(size_t)b1 * EE * SS + (size_t)col * SS + s1] = c[mi][nj][2];
                g_vT[(size_t)b1 * EE * SS + (size_t)(col + 1) * SS + s1] = c[mi][nj][3];
            }
    }
}

// ---------------- logits+exp: probs = exp(q/16 @ k^T) per (b,n,w).  grid (640,3) ----------------
__global__ __launch_bounds__(256) void logits_mma() {
    const int tid = threadIdx.x, lane = tid & 31, wid = tid >> 5;
    const int bn = blockIdx.x;
    const int b = bn >> 5, n = bn & 31;
    const int w = blockIdx.y;
    const int j = n - 1 + w;
    float* Lbase = g_probs + (size_t)bn * (BLK * CTX) + w * 128;

    if (j < 0 || j >= NB) {
        // padded context block: exp(0) = 1 (only the rowsum consumes these)
#pragma unroll
        for (int t = 0; t < 16; t++) {
            int f4 = tid + 256 * t;
            int row = f4 >> 5, c4 = f4 & 31;
            *(float4*)(Lbase + (size_t)row * CTX + c4 * 4) = make_float4(1.f, 1.f, 1.f, 1.f);
        }
        return;
    }

    extern __shared__ __align__(16) char dsm[];
    const int m_warp = (wid >> 1) * 32, n_warp = (wid & 1) * 64;
    const float* qsrc = g_q + (size_t)(b * SS + n * 128) * EE;
    const float* ksrc = g_k + (size_t)(b * SS + j * 128) * EE;
    char* buf[2] = {dsm, dsm + BUF_SZ};
    const uint32_t ub[2] = {smem_u32(buf[0]), smem_u32(buf[1])};

    float c[2][8][4];
#pragma unroll
    for (int i = 0; i < 2; i++)
#pragma unroll
        for (int jq = 0; jq < 8; jq++)
#pragma unroll
            for (int t = 0; t < 4; t++) c[i][jq][t] = 0.f;

    StageCvt sa, sb;
    ldg_cvt(sa, qsrc, EE, tid);
    ldg_cvt(sb, ksrc, EE, tid);
    sts_cvt(sa, buf[0] + BUF_AH, buf[0] + BUF_AL, tid);
    sts_cvt(sb, buf[0] + BUF_BH, buf[0] + BUF_BL, tid);
    __syncthreads();
    for (int kc = 0; kc < 8; kc++) {
        int cur = kc & 1, nxt = cur ^ 1;
        if (kc < 7) {
            ldg_cvt(sa, qsrc + (kc + 1) * 32, EE, tid);
            ldg_cvt(sb, ksrc + (kc + 1) * 32, EE, tid);
        }
        mma_chunk(ub[cur], lane, m_warp, n_warp, c);
        if (kc < 7) {
            sts_cvt(sa, buf[nxt] + BUF_AH, buf[nxt] + BUF_AL, tid);
            sts_cvt(sb, buf[nxt] + BUF_BH, buf[nxt] + BUF_BL, tid);
        }
        __syncthreads();
    }
#pragma unroll
    for (int mi = 0; mi < 2; mi++)
#pragma unroll
        for (int nj = 0; nj < 8; nj++) {
            int r = m_warp + mi * 16 + (lane >> 2);
            int col = n_warp + nj * 8 + (lane & 3) * 2;
            *(float2*)(Lbase + (size_t)r * CTX + col) =
                make_float2(__expf(c[mi][nj][0]), __expf(c[mi][nj][1]));
            *(float2*)(Lbase + (size_t)(r + 8) * CTX + col) =
                make_float2(__expf(c[mi][nj][2]), __expf(c[mi][nj][3]));
        }
}

// ---------------- rowsum: rinv = 1/sum(probs row).  one warp per row ----------------
__global__ __launch_bounds__(256) void rowsum_kernel() {
    const int gw = (blockIdx.x * blockDim.x + threadIdx.x) >> 5;
    const int lane = threadIdx.x & 31;
    const float* row = g_probs + (size_t)gw * CTX;
    float s = 0.f;
#pragma unroll
    for (int i = 0; i < 12; i++) s += row[lane + 32 * i];
#pragma unroll
    for (int o = 16; o > 0; o >>= 1) s += __shfl_xor_sync(0xFFFFFFFFu, s, o);
    if (lane == 0) g_rinv[gw] = 1.f / s;
}

// ---------------- AV: probs @ vT^T, normalized, permuted output.  grid (640,2) ----------------
__global__ __launch_bounds__(256) void av_mma() {
    extern __shared__ __align__(16) char dsm[];
    const int tid = threadIdx.x, lane = tid & 31, wid = tid >> 5;
    const int m_warp = (wid >> 1) * 32, n_warp = (wid & 1) * 64;
    const int bn = blockIdx.x;
    const int b = bn >> 5, n = bn & 31;
    const int n0 = blockIdx.y * 128;
    const float* psrc = g_probs + (size_t)bn * (BLK * CTX);
    const float* vsrc = g_vT + (size_t)b * EE * SS + (size_t)n0 * SS;
    char* buf[2] = {dsm, dsm + BUF_SZ};
    const uint32_t ub[2] = {smem_u32(buf[0]), smem_u32(buf[1])};

    // valid k-chunks (padded regions have v == 0 -> skip)
    int kcs[12], nk = 0;
#pragma unroll
    for (int kc = 0; kc < 12; kc++) {
        int key0 = (n - 1) * 128 + kc * 32;
        if (key0 >= 0 && key0 < SS) kcs[nk++] = kc;
    }

    float c[2][8][4];
#pragma unroll
    for (int i = 0; i < 2; i++)
#pragma unroll
        for (int jq = 0; jq < 8; jq++)
#pragma unroll
            for (int t = 0; t < 4; t++) c[i][jq][t] = 0.f;

    StageCvt sa, sb;
    ldg_cvt(sa, psrc + kcs[0] * 32, CTX, tid);
    ldg_cvt(sb, vsrc + (n - 1) * 128 + kcs[0] * 32, SS, tid);
    sts_cvt(sa, buf[0] + BUF_AH, buf[0] + BUF_AL, tid);
    sts_cvt(sb, buf[0] + BUF_BH, buf[0] + BUF_BL, tid);
    __syncthreads();
    for (int i = 0; i < nk; i++) {
        int cur = i & 1, nxt = cur ^ 1;
        if (i + 1 < nk) {
            ldg_cvt(sa, psrc + kcs[i + 1] * 32, CTX, tid);
            ldg_cvt(sb, vsrc + (n - 1) * 128 + kcs[i + 1] * 32, SS, tid);
        }
        mma_chunk(ub[cur], lane, m_warp, n_warp, c);
        if (i + 1 < nk) {
            sts_cvt(sa, buf[nxt] + BUF_AH, buf[nxt] + BUF_AL, tid);
            sts_cvt(sb, buf[nxt] + BUF_BH, buf[nxt] + BUF_BL, tid);
        }
        __syncthreads();
    }
    const int orow_base = n * (BB * 128) + b * 128;
#pragma unroll
    for (int mi = 0; mi < 2; mi++) {
        int rl = m_warp + mi * 16 + (lane >> 2);
        float ri0 = g_rinv[bn * 128 + rl];
        float ri1 = g_rinv[bn * 128 + rl + 8];
#pragma unroll
        for (int nj = 0; nj < 8; nj++) {
            int r = orow_base + rl;
            int col = n0 + n_warp + nj * 8 + (lane & 3) * 2;
            *(float2*)(g_att + (size_t)r * EE + col) =
                make_float2(c[mi][nj][0] * ri0, c[mi][nj][1] * ri0);
            *(float2*)(g_att + (size_t)(r + 8) * EE + col) =
                make_float2(c[mi][nj][2] * ri1, c[mi][nj][3] * ri1);
        }
    }
}

// ---------------- out-proj: att @ Wo + bo.  grid (640, 2) ----------------
__global__ __launch_bounds__(256) void out_mma(const float* __restrict__ bo,
                                               float* __restrict__ out) {
    extern __shared__ __align__(16) char dsm[];
    const int tid = threadIdx.x, lane = tid & 31, wid = tid >> 5;
    const int m_warp = (wid >> 1) * 32, n_warp = (wid & 1) * 64;
    const int m0 = blockIdx.x * 128;
    const int n0 = blockIdx.y * 128;
    const __nv_bfloat16* wh = g_wth[3] + (size_t)n0 * EE;
    const __nv_bfloat16* wl = g_wtl[3] + (size_t)n0 * EE;
    const float* asrc = g_att + (size_t)m0 * EE;
    char* buf[2] = {dsm, dsm + BUF_SZ};
    const uint32_t ub[2] = {smem_u32(buf[0]), smem_u32(buf[1])};

    float c[2][8][4];
#pragma unroll
    for (int i = 0; i < 2; i++)
#pragma unroll
        for (int jq = 0; jq < 8; jq++)
#pragma unroll
            for (int t = 0; t < 4; t++) c[i][jq][t] = 0.f;

    StageCvt sa; StageW sw;
    ldg_cvt(sa, asrc, EE, tid);
    ldg_w(sw, wh, wl, tid);
    sts_cvt(sa, buf[0] + BUF_AH, buf[0] + BUF_AL, tid);
    sts_w(sw, buf[0] + BUF_BH, buf[0] + BUF_BL, tid);
    __syncthreads();
    for (int kc = 0; kc < 8; kc++) {
        int cur = kc & 1, nxt = cur ^ 1;
        if (kc < 7) {
            ldg_cvt(sa, asrc + (kc + 1) * 32, EE, tid);
            ldg_w(sw, wh + (kc + 1) * 32, wl + (kc + 1) * 32, tid);
        }
        mma_chunk(ub[cur], lane, m_warp, n_warp, c);
        if (kc < 7) {
            sts_cvt(sa, buf[nxt] + BUF_AH, buf[nxt] + BUF_AL, tid);
            sts_w(sw, buf[nxt] + BUF_BH, buf[nxt] + BUF_BL, tid);
        }
        __syncthreads();
    }
#pragma unroll
    for (int mi = 0; mi < 2; mi++)
#pragma unroll
        for (int nj = 0; nj < 8; nj++) {
            int r = m0 + m_warp + mi * 16 + (lane >> 2);
            int col = n0 + n_warp + nj * 8 + (lane & 3) * 2;
            float2 bv = *(const float2*)(bo + col);
            *(float2*)(out + (size_t)r * EE + col) =
                make_float2(c[mi][nj][0] + bv.x, c[mi][nj][1] + bv.y);
            *(float2*)(out + (size_t)(r + 8) * EE + col) =
                make_float2(c[mi][nj][2] + bv.x, c[mi][nj][3] + bv.y);
        }
}

// ---------------- launch ----------------
extern "C" void kernel_launch(void* const* d_in, const int* in_sizes, int n_in,
                              void* d_out, int out_size) {
    const float* x  = (const float*)d_in[0];
    const float* Wq = (const float*)d_in[1];
    const float* Wk = (const float*)d_in[2];
    const float* Wv = (const float*)d_in[3];
    const float* Wo = (const float*)d_in[4];
    const float* bo = (const float*)d_in[5];
    float* out = (float*)d_out;

    static bool attr_done = false;
    if (!attr_done) {
        cudaFuncSetAttribute(qkv_mma, cudaFuncAttributeMaxDynamicSharedMemorySize, SMEM_PIPE);
        cudaFuncSetAttribute(logits_mma, cudaFuncAttributeMaxDynamicSharedMemorySize, SMEM_PIPE);
        cudaFuncSetAttribute(av_mma, cudaFuncAttributeMaxDynamicSharedMemorySize, SMEM_PIPE);
        cudaFuncSetAttribute(out_mma, cudaFuncAttributeMaxDynamicSharedMemorySize, SMEM_PIPE);
        attr_done = true;
    }

    prep_w<<<1024, 256>>>(Wq, Wk, Wv, Wo);
    qkv_mma<<<dim3(640, 6), 256, SMEM_PIPE>>>(x);
    logits_mma<<<dim3(640, 3), 256, SMEM_PIPE>>>();
    rowsum_kernel<<<10240, 256>>>();
    av_mma<<<dim3(640, 2), 256, SMEM_PIPE>>>();
    out_mma<<<dim3(640, 2), 256, SMEM_PIPE>>>(bo, out);
}